// round 1
// baseline (speedup 1.0000x reference)
#include <cuda_runtime.h>
#include <cuda_bf16.h>

#define Bv   4
#define Nv   25200
#define MAXD 100
#define NBv  5
#define ARv  14
#define MRv  56
#define ATT  (NBv*ARv*ARv)   // 980
#define PIX  (MRv*MRv)       // 3136

// Output layout (float32, tuple flattened in return order):
// [0,4)            num_det   (int->float)
// [4,1604)         det_boxes
// [1604,2004)      det_scores
// [2004,2404)      det_classes (int->float)
// [2404,2404+400*3136) masks_preds
#define OFF_BOX   4
#define OFF_SCR   (4 + Bv*MAXD*4)
#define OFF_CLS   (OFF_SCR + Bv*MAXD)
#define OFF_MSK   (OFF_CLS + Bv*MAXD)

__global__ __launch_bounds__(256) void mask2_fused_kernel(
    const float* __restrict__ attn,
    const int*   __restrict__ num_det,
    const float* __restrict__ det_boxes,
    const float* __restrict__ det_scores,
    const int*   __restrict__ det_classes,
    const int*   __restrict__ det_indices,
    const float* __restrict__ pooled,
    float*       __restrict__ out)
{
    if (blockIdx.x == 0) {
        // Pass-through outputs (2404 elements), casting ints to float.
        int t = threadIdx.x;
        if (t < Bv) out[t] = (float)num_det[t];
        for (int i = t; i < Bv*MAXD*4; i += blockDim.x) out[OFF_BOX + i] = det_boxes[i];
        for (int i = t; i < Bv*MAXD;   i += blockDim.x) out[OFF_SCR + i] = det_scores[i];
        for (int i = t; i < Bv*MAXD;   i += blockDim.x) out[OFF_CLS + i] = (float)det_classes[i];
        return;
    }

    const int d = blockIdx.x - 1;        // 0..399  (= b*MAXD + j, matches det_indices layout)
    const int b = d / MAXD;

    __shared__ float sa[ATT];            // gathered attn row: (5,14,14)
    const int idx = det_indices[d];
    const float* ap = attn + ((size_t)b * Nv + (size_t)idx) * ATT;
    for (int i = threadIdx.x; i < ATT; i += blockDim.x) sa[i] = ap[i];
    __syncthreads();

    const float* pb = pooled + (size_t)d * NBv * PIX;
    float*       op = out + OFF_MSK + (size_t)d * PIX;

    for (int p = threadIdx.x; p < PIX; p += blockDim.x) {
        const int y = p / MRv;
        const int x = p - y * MRv;

        // jax.image.resize bilinear (half-pixel centers, edge clamp):
        // c = (o + 0.5)*in/out - 0.5 = o*0.25 - 0.375
        float cx = x * 0.25f - 0.375f;
        float cy = y * 0.25f - 0.375f;
        float fx = floorf(cx), fy = floorf(cy);
        float wx = cx - fx,    wy = cy - fy;
        int ix0 = (int)fx, iy0 = (int)fy;
        int x0 = max(0, min(ARv - 1, ix0));
        int x1 = max(0, min(ARv - 1, ix0 + 1));
        int y0 = max(0, min(ARv - 1, iy0));
        int y1 = max(0, min(ARv - 1, iy0 + 1));

        const float w00 = (1.f - wx) * (1.f - wy);
        const float w01 = wx * (1.f - wy);
        const float w10 = (1.f - wx) * wy;
        const float w11 = wx * wy;

        const int o00 = y0 * ARv + x0, o01 = y0 * ARv + x1;
        const int o10 = y1 * ARv + x0, o11 = y1 * ARv + x1;

        float a[NBv];
        float m = -1e30f;
        #pragma unroll
        for (int c = 0; c < NBv; c++) {
            const float* s = sa + c * (ARv * ARv);
            float v = w00 * s[o00] + w01 * s[o01] + w10 * s[o10] + w11 * s[o11];
            a[c] = v;
            m = fmaxf(m, v);
        }

        float sum = 0.f, dot = 0.f;
        #pragma unroll
        for (int c = 0; c < NBv; c++) {
            float e = __expf(a[c] - m);
            sum += e;
            dot = fmaf(e, pb[(size_t)c * PIX + p], dot);  // coalesced plane reads
        }
        float z = dot / sum;                 // softmax-weighted sum
        op[p] = 1.f / (1.f + __expf(-z));    // sigmoid
    }
}

extern "C" void kernel_launch(void* const* d_in, const int* in_sizes, int n_in,
                              void* d_out, int out_size) {
    // metadata order: x0, attn, bases, num_det, det_boxes, det_scores,
    //                 det_classes, det_indices, pooled_bases
    const float* attn        = (const float*)d_in[1];
    const int*   num_det     = (const int*)  d_in[3];
    const float* det_boxes   = (const float*)d_in[4];
    const float* det_scores  = (const float*)d_in[5];
    const int*   det_classes = (const int*)  d_in[6];
    const int*   det_indices = (const int*)  d_in[7];
    const float* pooled      = (const float*)d_in[8];
    float* out = (float*)d_out;

    mask2_fused_kernel<<<Bv * MAXD + 1, 256>>>(
        attn, num_det, det_boxes, det_scores, det_classes,
        det_indices, pooled, out);
}

// round 2
// speedup vs baseline: 1.3538x; 1.3538x over previous
#include <cuda_runtime.h>
#include <cuda_bf16.h>

#define Bv   4
#define Nv   25200
#define MAXD 100
#define NBv  5
#define ARv  14
#define MRv  56
#define ATT  (NBv*ARv*ARv)     // 980
#define PIX  (MRv*MRv)         // 3136
#define V4PD (PIX/4)           // 784 float4 per detection
#define CHUNKS 4               // pixel chunks per detection
#define V4PC (V4PD/CHUNKS)     // 196 float4 per chunk

#define OFF_BOX   4
#define OFF_SCR   (4 + Bv*MAXD*4)
#define OFF_CLS   (OFF_SCR + Bv*MAXD)
#define OFF_MSK   (OFF_CLS + Bv*MAXD)

__global__ __launch_bounds__(256) void mask2_fused_kernel(
    const float* __restrict__ attn,
    const int*   __restrict__ num_det,
    const float* __restrict__ det_boxes,
    const float* __restrict__ det_scores,
    const int*   __restrict__ det_classes,
    const int*   __restrict__ det_indices,
    const float* __restrict__ pooled,
    float*       __restrict__ out)
{
    const int blk = blockIdx.x;
    if (blk == Bv * MAXD * CHUNKS) {
        // Pass-through outputs (2404 elements), vectorized where aligned.
        int t = threadIdx.x;
        if (t < Bv) out[t] = (float)num_det[t];
        const float4* bx4 = (const float4*)det_boxes;
        float4* ob4 = (float4*)(out + OFF_BOX);
        for (int i = t; i < Bv*MAXD; i += blockDim.x) ob4[i] = bx4[i];
        const float4* sc4 = (const float4*)det_scores;
        float4* os4 = (float4*)(out + OFF_SCR);
        for (int i = t; i < Bv*MAXD/4; i += blockDim.x) os4[i] = sc4[i];
        for (int i = t; i < Bv*MAXD; i += blockDim.x) out[OFF_CLS + i] = (float)det_classes[i];
        return;
    }

    const int d = blk >> 2;          // detection 0..399
    const int q = blk & 3;           // pixel chunk 0..3
    const int b = d / MAXD;

    __shared__ float sa[ATT];        // gathered attn row (5,14,14)
    {
        const int idx = __ldg(det_indices + d);
        const float4* ap4 = (const float4*)(attn + ((size_t)b * Nv + (size_t)idx) * ATT);
        float4* sa4 = (float4*)sa;
        if (threadIdx.x < ATT/4) sa4[threadIdx.x] = ap4[threadIdx.x];
    }
    __syncthreads();

    const int tid = threadIdx.x;
    if (tid >= V4PC) return;

    const int j = q * V4PC + tid;    // float4 item 0..783 within detection
    const int y = j / (MRv/4);       // output row 0..55
    const int m = j % (MRv/4);       // float4 column group 0..13 (x = 4m..4m+3)

    // Vertical: c = y*0.25 - 0.375, edge-clamped
    const float cy = y * 0.25f - 0.375f;
    const float fy = floorf(cy);
    const float wy = cy - fy;
    const int iy = (int)fy;
    const int y0 = max(0, min(ARv - 1, iy));
    const int y1 = max(0, min(ARv - 1, iy + 1));

    // Horizontal taps: columns {m-1, m, m+1} (clamped), constant weights
    const int cm1 = max(m - 1, 0);
    const int c0  = m;
    const int cp1 = min(m + 1, ARv - 1);

    const float4* pb4 = (const float4*)(pooled + (size_t)d * NBv * PIX);

    float a0[NBv], a1[NBv], a2[NBv], a3[NBv];
    float4 pv[NBv];
    #pragma unroll
    for (int c = 0; c < NBv; c++) pv[c] = pb4[c * V4PD + j];

    #pragma unroll
    for (int c = 0; c < NBv; c++) {
        const float* s0 = sa + c * (ARv*ARv) + y0 * ARv;
        const float* s1 = sa + c * (ARv*ARv) + y1 * ARv;
        float u0 = fmaf(wy, s1[cm1] - s0[cm1], s0[cm1]);
        float u1 = fmaf(wy, s1[c0]  - s0[c0],  s0[c0]);
        float u2 = fmaf(wy, s1[cp1] - s0[cp1], s0[cp1]);
        a0[c] = fmaf(0.375f, u0, 0.625f * u1);   // x=4m   : wx=0.625, taps (m-1,m)
        a1[c] = fmaf(0.125f, u0, 0.875f * u1);   // x=4m+1 : wx=0.875, taps (m-1,m)
        a2[c] = fmaf(0.125f, u2, 0.875f * u1);   // x=4m+2 : wx=0.125, taps (m,m+1)
        a3[c] = fmaf(0.375f, u2, 0.625f * u1);   // x=4m+3 : wx=0.375, taps (m,m+1)
    }

    float4 res;
    {
        float s = 0.f, dt = 0.f;
        #pragma unroll
        for (int c = 0; c < NBv; c++) { float e = __expf(a0[c]); s += e; dt = fmaf(e, pv[c].x, dt); }
        float z = __fdividef(dt, s);
        res.x = __fdividef(1.f, 1.f + __expf(-z));
    }
    {
        float s = 0.f, dt = 0.f;
        #pragma unroll
        for (int c = 0; c < NBv; c++) { float e = __expf(a1[c]); s += e; dt = fmaf(e, pv[c].y, dt); }
        float z = __fdividef(dt, s);
        res.y = __fdividef(1.f, 1.f + __expf(-z));
    }
    {
        float s = 0.f, dt = 0.f;
        #pragma unroll
        for (int c = 0; c < NBv; c++) { float e = __expf(a2[c]); s += e; dt = fmaf(e, pv[c].z, dt); }
        float z = __fdividef(dt, s);
        res.z = __fdividef(1.f, 1.f + __expf(-z));
    }
    {
        float s = 0.f, dt = 0.f;
        #pragma unroll
        for (int c = 0; c < NBv; c++) { float e = __expf(a3[c]); s += e; dt = fmaf(e, pv[c].w, dt); }
        float z = __fdividef(dt, s);
        res.w = __fdividef(1.f, 1.f + __expf(-z));
    }

    float4* op4 = (float4*)(out + OFF_MSK + (size_t)d * PIX);
    op4[j] = res;
}

extern "C" void kernel_launch(void* const* d_in, const int* in_sizes, int n_in,
                              void* d_out, int out_size) {
    const float* attn        = (const float*)d_in[1];
    const int*   num_det     = (const int*)  d_in[3];
    const float* det_boxes   = (const float*)d_in[4];
    const float* det_scores  = (const float*)d_in[5];
    const int*   det_classes = (const int*)  d_in[6];
    const int*   det_indices = (const int*)  d_in[7];
    const float* pooled      = (const float*)d_in[8];
    float* out = (float*)d_out;

    mask2_fused_kernel<<<Bv * MAXD * CHUNKS + 1, 256>>>(
        attn, num_det, det_boxes, det_scores, det_classes,
        det_indices, pooled, out);
}

// round 3
// speedup vs baseline: 1.3780x; 1.0179x over previous
#include <cuda_runtime.h>
#include <cuda_bf16.h>

#define Bv   4
#define Nv   25200
#define MAXD 100
#define NBv  5
#define ARv  14
#define MRv  56
#define ATT  (NBv*ARv*ARv)     // 980
#define PIX  (MRv*MRv)         // 3136
#define V4PD (PIX/4)           // 784 float4 per detection

#define OFF_BOX   4
#define OFF_SCR   (4 + Bv*MAXD*4)
#define OFF_CLS   (OFF_SCR + Bv*MAXD)
#define OFF_MSK   (OFF_CLS + Bv*MAXD)

// Compute one float4 (4 horizontally-adjacent output pixels) given the smem
// attn tile and the 5 prefetched pooled float4s. Bilinear 14->56, scale=4,
// half-pixel centers: horizontal weights are compile-time constants.
__device__ __forceinline__ float4 compute_item(int j, const float* __restrict__ sa,
                                               const float4* __restrict__ pv)
{
    const int y = j / (MRv/4 * 4 / 4);        // j / 14
    const int m = j - y * (MRv/4);            // 0..13

    const float cy = y * 0.25f - 0.375f;
    const float fy = floorf(cy);
    const float wy = cy - fy;
    const int iy = (int)fy;
    const int y0 = max(0, min(ARv - 1, iy));
    const int y1 = max(0, min(ARv - 1, iy + 1));

    const int cm1 = max(m - 1, 0);
    const int c0  = m;
    const int cp1 = min(m + 1, ARv - 1);

    float a0[NBv], a1[NBv], a2[NBv], a3[NBv];
    #pragma unroll
    for (int c = 0; c < NBv; c++) {
        const float* s0 = sa + c * (ARv*ARv) + y0 * ARv;
        const float* s1 = sa + c * (ARv*ARv) + y1 * ARv;
        float u0 = fmaf(wy, s1[cm1] - s0[cm1], s0[cm1]);
        float u1 = fmaf(wy, s1[c0]  - s0[c0],  s0[c0]);
        float u2 = fmaf(wy, s1[cp1] - s0[cp1], s0[cp1]);
        a0[c] = fmaf(0.375f, u0, 0.625f * u1);
        a1[c] = fmaf(0.125f, u0, 0.875f * u1);
        a2[c] = fmaf(0.125f, u2, 0.875f * u1);
        a3[c] = fmaf(0.375f, u2, 0.625f * u1);
    }

    float4 res;
    {
        float s = 0.f, dt = 0.f;
        #pragma unroll
        for (int c = 0; c < NBv; c++) { float e = __expf(a0[c]); s += e; dt = fmaf(e, pv[c].x, dt); }
        float z = __fdividef(dt, s);
        res.x = __fdividef(1.f, 1.f + __expf(-z));
    }
    {
        float s = 0.f, dt = 0.f;
        #pragma unroll
        for (int c = 0; c < NBv; c++) { float e = __expf(a1[c]); s += e; dt = fmaf(e, pv[c].y, dt); }
        float z = __fdividef(dt, s);
        res.y = __fdividef(1.f, 1.f + __expf(-z));
    }
    {
        float s = 0.f, dt = 0.f;
        #pragma unroll
        for (int c = 0; c < NBv; c++) { float e = __expf(a2[c]); s += e; dt = fmaf(e, pv[c].z, dt); }
        float z = __fdividef(dt, s);
        res.z = __fdividef(1.f, 1.f + __expf(-z));
    }
    {
        float s = 0.f, dt = 0.f;
        #pragma unroll
        for (int c = 0; c < NBv; c++) { float e = __expf(a3[c]); s += e; dt = fmaf(e, pv[c].w, dt); }
        float z = __fdividef(dt, s);
        res.w = __fdividef(1.f, 1.f + __expf(-z));
    }
    return res;
}

__global__ __launch_bounds__(256, 3) void mask2_fused_kernel(
    const float* __restrict__ attn,
    const int*   __restrict__ num_det,
    const float* __restrict__ det_boxes,
    const float* __restrict__ det_scores,
    const int*   __restrict__ det_classes,
    const int*   __restrict__ det_indices,
    const float* __restrict__ pooled,
    float*       __restrict__ out)
{
    const int blk = blockIdx.x;
    if (blk == Bv * MAXD) {
        int t = threadIdx.x;
        if (t < Bv) out[t] = (float)num_det[t];
        const float4* bx4 = (const float4*)det_boxes;
        float4* ob4 = (float4*)(out + OFF_BOX);
        for (int i = t; i < Bv*MAXD; i += blockDim.x) ob4[i] = bx4[i];
        const float4* sc4 = (const float4*)det_scores;
        float4* os4 = (float4*)(out + OFF_SCR);
        for (int i = t; i < Bv*MAXD/4; i += blockDim.x) os4[i] = sc4[i];
        for (int i = t; i < Bv*MAXD; i += blockDim.x) out[OFF_CLS + i] = (float)det_classes[i];
        return;
    }

    const int d = blk;                 // detection 0..399
    const int b = d / MAXD;
    const int tid = threadIdx.x;

    const float4* pb4 = (const float4*)(pooled + (size_t)d * NBv * PIX);
    float4* op4 = (float4*)(out + OFF_MSK + (size_t)d * PIX);

    // Items: j0=tid, j1=tid+256, j2=tid+512 (all valid: max 767 < 784),
    //        j3=tid+768 (valid for tid < 16).
    const int j0 = tid, j1 = tid + 256, j2 = tid + 512, j3 = tid + 768;

    // ---- Prefetch pooled planes for items 0 and 1 BEFORE the barrier ----
    float4 pv0[NBv], pv1[NBv];
    #pragma unroll
    for (int c = 0; c < NBv; c++) pv0[c] = pb4[c * V4PD + j0];
    #pragma unroll
    for (int c = 0; c < NBv; c++) pv1[c] = pb4[c * V4PD + j1];

    // ---- Gather attn row into smem (overlaps with the prefetch above) ----
    __shared__ float sa[ATT];
    {
        const int idx = __ldg(det_indices + d);
        const float4* ap4 = (const float4*)(attn + ((size_t)b * Nv + (size_t)idx) * ATT);
        if (tid < ATT/4) ((float4*)sa)[tid] = ap4[tid];
    }
    __syncthreads();

    op4[j0] = compute_item(j0, sa, pv0);
    op4[j1] = compute_item(j1, sa, pv1);

    // Item 2 (and 3 for first 16 threads): load then compute.
    float4 pv2[NBv];
    #pragma unroll
    for (int c = 0; c < NBv; c++) pv2[c] = pb4[c * V4PD + j2];
    if (tid < PIX/4 - 768) {
        float4 pv3[NBv];
        #pragma unroll
        for (int c = 0; c < NBv; c++) pv3[c] = pb4[c * V4PD + j3];
        op4[j2] = compute_item(j2, sa, pv2);
        op4[j3] = compute_item(j3, sa, pv3);
    } else {
        op4[j2] = compute_item(j2, sa, pv2);
    }
}

extern "C" void kernel_launch(void* const* d_in, const int* in_sizes, int n_in,
                              void* d_out, int out_size) {
    const float* attn        = (const float*)d_in[1];
    const int*   num_det     = (const int*)  d_in[3];
    const float* det_boxes   = (const float*)d_in[4];
    const float* det_scores  = (const float*)d_in[5];
    const int*   det_classes = (const int*)  d_in[6];
    const int*   det_indices = (const int*)  d_in[7];
    const float* pooled      = (const float*)d_in[8];
    float* out = (float*)d_out;

    mask2_fused_kernel<<<Bv * MAXD + 1, 256>>>(
        attn, num_det, det_boxes, det_scores, det_classes,
        det_indices, pooled, out);
}

// round 4
// speedup vs baseline: 1.3821x; 1.0030x over previous
#include <cuda_runtime.h>
#include <cuda_bf16.h>

#define Bv   4
#define Nv   25200
#define MAXD 100
#define NBv  5
#define ARv  14
#define MRv  56
#define ATT  (NBv*ARv*ARv)     // 980
#define PIX  (MRv*MRv)         // 3136
#define V4PD (PIX/4)           // 784 float4 per detection
#define HALF (V4PD/2)          // 392 float4 per half
#define SROWS 8                // src rows gathered per half
#define SCH  (SROWS*ARv)       // 112 floats per channel in smem

#define OFF_BOX   4
#define OFF_SCR   (4 + Bv*MAXD*4)
#define OFF_CLS   (OFF_SCR + Bv*MAXD)
#define OFF_MSK   (OFF_CLS + Bv*MAXD)

// One float4 = 4 horizontally-adjacent output pixels. Bilinear 14->56,
// half-pixel centers; horizontal weights are compile-time constants.
// sa holds 8 src rows per channel, offset by 6*h rows from global.
__device__ __forceinline__ float4 compute_item(int j, int rowoff,
                                               const float* __restrict__ sa,
                                               const float4* __restrict__ pv)
{
    const int y = j / (MRv/4);            // global output row 0..55
    const int m = j - y * (MRv/4);        // float4 col group 0..13

    const float cy = y * 0.25f - 0.375f;
    const float fy = floorf(cy);
    const float wy = cy - fy;
    const int iy = (int)fy;
    const int r0 = max(0, min(ARv - 1, iy))     - rowoff;  // 0..7 in smem
    const int r1 = max(0, min(ARv - 1, iy + 1)) - rowoff;

    const int cm1 = max(m - 1, 0);
    const int c0  = m;
    const int cp1 = min(m + 1, ARv - 1);

    float a0[NBv], a1[NBv], a2[NBv], a3[NBv];
    #pragma unroll
    for (int c = 0; c < NBv; c++) {
        const float* s0 = sa + c * SCH + r0 * ARv;
        const float* s1 = sa + c * SCH + r1 * ARv;
        float u0 = fmaf(wy, s1[cm1] - s0[cm1], s0[cm1]);
        float u1 = fmaf(wy, s1[c0]  - s0[c0],  s0[c0]);
        float u2 = fmaf(wy, s1[cp1] - s0[cp1], s0[cp1]);
        a0[c] = fmaf(0.375f, u0, 0.625f * u1);
        a1[c] = fmaf(0.125f, u0, 0.875f * u1);
        a2[c] = fmaf(0.125f, u2, 0.875f * u1);
        a3[c] = fmaf(0.375f, u2, 0.625f * u1);
    }

    float4 res;
    {
        float s = 0.f, dt = 0.f;
        #pragma unroll
        for (int c = 0; c < NBv; c++) { float e = __expf(a0[c]); s += e; dt = fmaf(e, pv[c].x, dt); }
        float z = __fdividef(dt, s);
        res.x = __fdividef(1.f, 1.f + __expf(-z));
    }
    {
        float s = 0.f, dt = 0.f;
        #pragma unroll
        for (int c = 0; c < NBv; c++) { float e = __expf(a1[c]); s += e; dt = fmaf(e, pv[c].y, dt); }
        float z = __fdividef(dt, s);
        res.y = __fdividef(1.f, 1.f + __expf(-z));
    }
    {
        float s = 0.f, dt = 0.f;
        #pragma unroll
        for (int c = 0; c < NBv; c++) { float e = __expf(a2[c]); s += e; dt = fmaf(e, pv[c].z, dt); }
        float z = __fdividef(dt, s);
        res.z = __fdividef(1.f, 1.f + __expf(-z));
    }
    {
        float s = 0.f, dt = 0.f;
        #pragma unroll
        for (int c = 0; c < NBv; c++) { float e = __expf(a3[c]); s += e; dt = fmaf(e, pv[c].w, dt); }
        float z = __fdividef(dt, s);
        res.w = __fdividef(1.f, 1.f + __expf(-z));
    }
    return res;
}

__global__ __launch_bounds__(256, 4) void mask2_fused_kernel(
    const float* __restrict__ attn,
    const int*   __restrict__ num_det,
    const float* __restrict__ det_boxes,
    const float* __restrict__ det_scores,
    const int*   __restrict__ det_classes,
    const int*   __restrict__ det_indices,
    const float* __restrict__ pooled,
    float*       __restrict__ out)
{
    const int blk = blockIdx.x;
    if (blk == 2 * Bv * MAXD) {
        int t = threadIdx.x;
        if (t < Bv) out[t] = (float)num_det[t];
        const float4* bx4 = (const float4*)det_boxes;
        float4* ob4 = (float4*)(out + OFF_BOX);
        for (int i = t; i < Bv*MAXD; i += blockDim.x) ob4[i] = bx4[i];
        const float4* sc4 = (const float4*)det_scores;
        float4* os4 = (float4*)(out + OFF_SCR);
        for (int i = t; i < Bv*MAXD/4; i += blockDim.x) os4[i] = sc4[i];
        for (int i = t; i < Bv*MAXD; i += blockDim.x) out[OFF_CLS + i] = (float)det_classes[i];
        return;
    }

    const int d = blk >> 1;            // detection 0..399
    const int h = blk & 1;             // half: output rows [28h, 28h+28)
    const int b = d / MAXD;
    const int tid = threadIdx.x;

    const float4* pb4 = (const float4*)(pooled + (size_t)d * NBv * PIX);
    float4* op4 = (float4*)(out + OFF_MSK + (size_t)d * PIX);

    const int j0 = h * HALF + tid;            // always valid
    const int j1 = j0 + 256;                  // valid for tid < HALF-256 = 136
    const bool has1 = tid < (HALF - 256);

    // ---- Prefetch pooled planes BEFORE the barrier ----
    float4 pv0[NBv], pv1[NBv];
    #pragma unroll
    for (int c = 0; c < NBv; c++) pv0[c] = pb4[c * V4PD + j0];
    if (has1) {
        #pragma unroll
        for (int c = 0; c < NBv; c++) pv1[c] = pb4[c * V4PD + j1];
    }

    // ---- Gather only the 8 needed src rows per channel (560 floats) ----
    // half 0 -> src rows 0..7, half 1 -> src rows 6..13 (offset 6h rows = 21 float4)
    __shared__ float sa[NBv * SCH];
    {
        const int idx = __ldg(det_indices + d);
        const float4* ap4 = (const float4*)(attn + ((size_t)b * Nv + (size_t)idx) * ATT);
        if (tid < NBv * SCH / 4) {            // 140 float4
            const int ch = tid / (SCH/4);     // /28
            const int rf = tid - ch * (SCH/4);
            ((float4*)sa)[tid] = ap4[ch * (ARv*ARv/4) + h * (6*ARv/4) + rf];
        }
    }
    __syncthreads();

    const int rowoff = 6 * h;
    op4[j0] = compute_item(j0, rowoff, sa, pv0);
    if (has1) op4[j1] = compute_item(j1, rowoff, sa, pv1);
}

extern "C" void kernel_launch(void* const* d_in, const int* in_sizes, int n_in,
                              void* d_out, int out_size) {
    const float* attn        = (const float*)d_in[1];
    const int*   num_det     = (const int*)  d_in[3];
    const float* det_boxes   = (const float*)d_in[4];
    const float* det_scores  = (const float*)d_in[5];
    const int*   det_classes = (const int*)  d_in[6];
    const int*   det_indices = (const int*)  d_in[7];
    const float* pooled      = (const float*)d_in[8];
    float* out = (float*)d_out;

    mask2_fused_kernel<<<2 * Bv * MAXD + 1, 256>>>(
        attn, num_det, det_boxes, det_scores, det_classes,
        det_indices, pooled, out);
}